// round 4
// baseline (speedup 1.0000x reference)
#include <cuda_runtime.h>
#include <cuda_bf16.h>
#include <cstdint>
#include <cstddef>

#define IN_F 4096
#define OUT_F 11008
#define TOK 32
#define NELEM (OUT_F * IN_F)     /* 45,088,768 */
#define N4 (NELEM / 4)           /* 11,272,192 */
#define RBLOCKS 1184

/* x chunking for the GEMM: CK k-columns staged in SMEM at a time,
   row padded by 8 bf16 (16B) for conflict-free ldmatrix. */
#define CK 1024
#define PK (CK + 8)
#define GEMM_SMEM (2 * TOK * PK * 2)   /* hi + lo, bf16: 132,096 B */

/* ------------------------------------------------------------------ */
/* device globals (scratch — no allocations allowed)                   */
/* ------------------------------------------------------------------ */
__device__ float          g_partials[RBLOCKS];
__device__ float          g_scale;
__device__ unsigned       g_thr_bits;
__device__ __nv_bfloat16  g_xhi[TOK * IN_F];
__device__ __nv_bfloat16  g_xlo[TOK * IN_F];

/* ------------------------------------------------------------------ */
__device__ __forceinline__ uint32_t smem_u32(const void* p) {
    uint32_t a;
    asm("{ .reg .u64 t; cvta.to.shared.u64 t, %1; cvt.u32.u64 %0, t; }"
        : "=r"(a) : "l"(p));
    return a;
}

/* ternarize one fp32 (bit pattern) -> bf16 half in {0xBF80, 0x0000, 0x3F80} */
__device__ __forceinline__ uint32_t tern(uint32_t u, uint32_t thr) {
    uint32_t h = 0x3F80u | ((u >> 16) & 0x8000u);
    return ((u & 0x7FFFFFFFu) > thr) ? h : 0u;
}

/* pack two ternary bf16 (k, k+1) into one .b32 mma operand */
__device__ __forceinline__ uint32_t tpack(float a, float b, uint32_t thr) {
    return __byte_perm(tern(__float_as_uint(a), thr),
                       tern(__float_as_uint(b), thr), 0x5410);
}

__device__ __forceinline__ void ldsm_x4(uint32_t* r, uint32_t addr) {
    asm volatile("ldmatrix.sync.aligned.m8n8.x4.shared.b16 {%0,%1,%2,%3}, [%4];"
                 : "=r"(r[0]), "=r"(r[1]), "=r"(r[2]), "=r"(r[3]) : "r"(addr));
}

__device__ __forceinline__ void mma_bf16(float* d, const uint32_t* a,
                                         uint32_t b0, uint32_t b1) {
    asm volatile(
        "mma.sync.aligned.m16n8k16.row.col.f32.bf16.bf16.f32 "
        "{%0,%1,%2,%3}, {%4,%5,%6,%7}, {%8,%9}, {%0,%1,%2,%3};"
        : "+f"(d[0]), "+f"(d[1]), "+f"(d[2]), "+f"(d[3])
        : "r"(a[0]), "r"(a[1]), "r"(a[2]), "r"(a[3]), "r"(b0), "r"(b1));
}

/* ------------------------------------------------------------------ */
/* pass 1: abs-sum partials over W                                     */
/* ------------------------------------------------------------------ */
__global__ void k_reduce(const float* __restrict__ w) {
    __shared__ float sm[256];
    const float4* w4 = reinterpret_cast<const float4*>(w);
    int idx = blockIdx.x * 256 + threadIdx.x;
    int stride = gridDim.x * 256;
    float s0 = 0.f, s1 = 0.f, s2 = 0.f, s3 = 0.f;
    int i = idx;
    for (; i + 3 * stride < N4; i += 4 * stride) {
        float4 a = w4[i];
        float4 b = w4[i + stride];
        float4 c = w4[i + 2 * stride];
        float4 d = w4[i + 3 * stride];
        s0 += fabsf(a.x) + fabsf(a.y) + fabsf(a.z) + fabsf(a.w);
        s1 += fabsf(b.x) + fabsf(b.y) + fabsf(b.z) + fabsf(b.w);
        s2 += fabsf(c.x) + fabsf(c.y) + fabsf(c.z) + fabsf(c.w);
        s3 += fabsf(d.x) + fabsf(d.y) + fabsf(d.z) + fabsf(d.w);
    }
    for (; i < N4; i += stride) {
        float4 a = w4[i];
        s0 += fabsf(a.x) + fabsf(a.y) + fabsf(a.z) + fabsf(a.w);
    }
    sm[threadIdx.x] = (s0 + s1) + (s2 + s3);
    __syncthreads();
    for (int o = 128; o > 0; o >>= 1) {
        if (threadIdx.x < o) sm[threadIdx.x] += sm[threadIdx.x + o];
        __syncthreads();
    }
    if (threadIdx.x == 0) g_partials[blockIdx.x] = sm[0];
}

/* ------------------------------------------------------------------ */
/* pass 2: finish reduction in double, publish scale + threshold bits  */
/* ------------------------------------------------------------------ */
__global__ void k_finalize() {
    __shared__ double sd[256];
    double s = 0.0;
    for (int i = threadIdx.x; i < RBLOCKS; i += 256) s += (double)g_partials[i];
    sd[threadIdx.x] = s;
    __syncthreads();
    for (int o = 128; o > 0; o >>= 1) {
        if (threadIdx.x < o) sd[threadIdx.x] += sd[threadIdx.x + o];
        __syncthreads();
    }
    if (threadIdx.x == 0) {
        double mean = sd[0] / (double)NELEM;
        float am = fmaxf((float)mean, 1e-5f);
        g_scale = am;
        g_thr_bits = __float_as_uint(0.7f * am);
    }
}

/* ------------------------------------------------------------------ */
/* pass 3: split x into bf16 hi/lo                                     */
/* ------------------------------------------------------------------ */
__global__ void k_xsplit(const float* __restrict__ x) {
    int i = blockIdx.x * blockDim.x + threadIdx.x;
    if (i < TOK * IN_F) {
        float v = x[i];
        __nv_bfloat16 h = __float2bfloat16(v);
        g_xhi[i] = h;
        g_xlo[i] = __float2bfloat16(v - __bfloat162float(h));
    }
}

/* ------------------------------------------------------------------ */
/* pass 4: dequant-GEMM via mma.sync m16n8k16 bf16.                    */
/* grid = 86 CTAs x 256 thr. CTA covers 128 outputs x 32 tokens.       */
/* Each warp: 16 outputs (2 n8 tiles) x 32 tokens (2 m16 tiles).       */
/* W ternarized in registers -> B fragments; x hi/lo via ldmatrix.     */
/* ------------------------------------------------------------------ */
__global__ __launch_bounds__(256, 1) void k_gemm(const float* __restrict__ w,
                                                 float* __restrict__ out) {
    extern __shared__ __align__(16) char smem[];
    uint32_t sbase = smem_u32(smem);
    const uint32_t lo_off = TOK * PK * 2;          /* bytes to lo buffer */

    const int tid = threadIdx.x;
    const int lane = tid & 31;
    const int wid = tid >> 5;

    const uint32_t thr = g_thr_bits;
    const int o_base = blockIdx.x * 128 + wid * 16;
    const int kq = 2 * (lane & 3);                  /* k offset pair */
    const int nrow = lane >> 2;                     /* output within n8 */

    const float* w0 = w + (size_t)(o_base + nrow) * IN_F;
    const float* w1 = w0 + (size_t)8 * IN_F;

    /* ldmatrix per-thread source row/col inside a 16x16 A tile */
    const int mrow = ((lane >> 3) & 1) * 8 + (lane & 7);
    const int mcol = (lane >> 4) * 8;
    /* byte address of this thread's ldmatrix row for token-tile tt:
       tok = tt*16 + mrow, col = mcol (+kk per step) */
    const uint32_t am0 = sbase + (uint32_t)((0 * 16 + mrow) * PK + mcol) * 2;
    const uint32_t am1 = sbase + (uint32_t)((1 * 16 + mrow) * PK + mcol) * 2;

    float acc[2][2][4];
#pragma unroll
    for (int t = 0; t < 2; t++)
#pragma unroll
        for (int n = 0; n < 2; n++)
#pragma unroll
            for (int r = 0; r < 4; r++) acc[t][n][r] = 0.f;

    for (int c0 = 0; c0 < IN_F; c0 += CK) {
        /* ---- stage x chunk (hi & lo) into padded SMEM ---- */
        {
            const uint4* srch = reinterpret_cast<const uint4*>(g_xhi);
            const uint4* srcl = reinterpret_cast<const uint4*>(g_xlo);
#pragma unroll
            for (int e = 0; e < (TOK * CK / 8) / 256; e++) {
                int g = e * 256 + tid;              /* 8-elem group id */
                int tok = g / (CK / 8);
                int kg = g % (CK / 8);
                uint4 hv = srch[(tok * IN_F + c0) / 8 + kg];
                uint4 lv = srcl[(tok * IN_F + c0) / 8 + kg];
                uint32_t dst = sbase + (uint32_t)(tok * PK + kg * 8) * 2;
                asm volatile("st.shared.v4.b32 [%0], {%1,%2,%3,%4};"
                             :: "r"(dst), "r"(hv.x), "r"(hv.y), "r"(hv.z), "r"(hv.w)
                             : "memory");
                asm volatile("st.shared.v4.b32 [%0], {%1,%2,%3,%4};"
                             :: "r"(dst + lo_off), "r"(lv.x), "r"(lv.y), "r"(lv.z), "r"(lv.w)
                             : "memory");
            }
        }
        __syncthreads();

#pragma unroll 4
        for (int kk = 0; kk < CK; kk += 16) {
            const int k = c0 + kk;

            /* W loads first: four independent LDG.64 to cover DRAM latency */
            float2 u00 = *reinterpret_cast<const float2*>(w0 + k + kq);
            float2 u01 = *reinterpret_cast<const float2*>(w0 + k + kq + 8);
            float2 u10 = *reinterpret_cast<const float2*>(w1 + k + kq);
            float2 u11 = *reinterpret_cast<const float2*>(w1 + k + kq + 8);

            /* A fragments for both token tiles, hi and lo */
            uint32_t ah0[4], ah1[4], al0[4], al1[4];
            ldsm_x4(ah0, am0 + kk * 2);
            ldsm_x4(ah1, am1 + kk * 2);
            ldsm_x4(al0, am0 + kk * 2 + lo_off);
            ldsm_x4(al1, am1 + kk * 2 + lo_off);

            /* ternarize -> B fragments */
            uint32_t b00 = tpack(u00.x, u00.y, thr);
            uint32_t b01 = tpack(u01.x, u01.y, thr);
            uint32_t b10 = tpack(u10.x, u10.y, thr);
            uint32_t b11 = tpack(u11.x, u11.y, thr);

            mma_bf16(acc[0][0], ah0, b00, b01);
            mma_bf16(acc[1][0], ah1, b00, b01);
            mma_bf16(acc[0][1], ah0, b10, b11);
            mma_bf16(acc[1][1], ah1, b10, b11);
            mma_bf16(acc[0][0], al0, b00, b01);
            mma_bf16(acc[1][0], al1, b00, b01);
            mma_bf16(acc[0][1], al0, b10, b11);
            mma_bf16(acc[1][1], al1, b10, b11);
        }
        __syncthreads();
    }

    /* ---- epilogue: scale and store ---- */
    const float scale = g_scale;
#pragma unroll
    for (int tt = 0; tt < 2; tt++) {
#pragma unroll
        for (int nt = 0; nt < 2; nt++) {
            int tok = tt * 16 + (lane >> 2);
            int o = o_base + nt * 8 + kq;
            float2 lo2, hi2;
            lo2.x = scale * acc[tt][nt][0];
            lo2.y = scale * acc[tt][nt][1];
            hi2.x = scale * acc[tt][nt][2];
            hi2.y = scale * acc[tt][nt][3];
            *reinterpret_cast<float2*>(out + (size_t)tok * OUT_F + o) = lo2;
            *reinterpret_cast<float2*>(out + (size_t)(tok + 8) * OUT_F + o) = hi2;
        }
    }
}

/* ------------------------------------------------------------------ */
extern "C" void kernel_launch(void* const* d_in, const int* in_sizes, int n_in,
                              void* d_out, int out_size) {
    const float* x = (const float*)d_in[0];
    const float* w = (const float*)d_in[1];
    float* out = (float*)d_out;
    (void)in_sizes; (void)n_in; (void)out_size;

    cudaFuncSetAttribute(k_gemm, cudaFuncAttributeMaxDynamicSharedMemorySize,
                         GEMM_SMEM);

    k_reduce<<<RBLOCKS, 256>>>(w);
    k_finalize<<<1, 256>>>();
    k_xsplit<<<(TOK * IN_F + 255) / 256, 256>>>(x);
    k_gemm<<<OUT_F / 128, 256, GEMM_SMEM>>>(w, out);
}

// round 8
// speedup vs baseline: 1.2682x; 1.2682x over previous
#include <cuda_runtime.h>
#include <cuda_bf16.h>
#include <cstdint>
#include <cstddef>

#define IN_F 4096
#define OUT_F 11008
#define TOK 32
#define NELEM (OUT_F * IN_F)     /* 45,088,768 */
#define N4 (NELEM / 4)           /* 11,272,192 */
#define RBLOCKS 1184

#define MTILES 86                /* OUT_F / 128 */
#define SPLITS 8
#define KSP (IN_F / SPLITS)      /* 512 k per item */
#define PK (KSP + 8)             /* padded row: conflict-free ldmatrix */
#define GEMM_SMEM (2 * TOK * PK * 2)   /* hi+lo bf16: 66,560 B */

/* ------------------------------------------------------------------ */
/* device globals (scratch — no allocations allowed)                   */
/* ------------------------------------------------------------------ */
__device__ float                        g_partials[RBLOCKS];
__device__ float                        g_scale;
__device__ unsigned                     g_thr_bits;
__device__ __align__(16) __nv_bfloat16  g_xhi[TOK * IN_F];
__device__ __align__(16) __nv_bfloat16  g_xlo[TOK * IN_F];
__device__ float                        g_part[SPLITS][TOK * OUT_F];

/* ------------------------------------------------------------------ */
__device__ __forceinline__ uint32_t smem_u32(const void* p) {
    uint32_t a;
    asm("{ .reg .u64 t; cvta.to.shared.u64 t, %1; cvt.u32.u64 %0, t; }"
        : "=r"(a) : "l"(p));
    return a;
}

/* ternarize one fp32 (bit pattern) -> bf16 half in {0xBF80, 0x0000, 0x3F80} */
__device__ __forceinline__ uint32_t tern(uint32_t u, uint32_t thr) {
    uint32_t h = 0x3F80u | ((u >> 16) & 0x8000u);
    return ((u & 0x7FFFFFFFu) > thr) ? h : 0u;
}

__device__ __forceinline__ uint32_t tpack(float a, float b, uint32_t thr) {
    return __byte_perm(tern(__float_as_uint(a), thr),
                       tern(__float_as_uint(b), thr), 0x5410);
}

__device__ __forceinline__ void ldsm_x4(uint32_t* r, uint32_t addr) {
    asm volatile("ldmatrix.sync.aligned.m8n8.x4.shared.b16 {%0,%1,%2,%3}, [%4];"
                 : "=r"(r[0]), "=r"(r[1]), "=r"(r[2]), "=r"(r[3]) : "r"(addr));
}

__device__ __forceinline__ void mma_bf16(float* d, const uint32_t* a,
                                         uint32_t b0, uint32_t b1) {
    asm volatile(
        "mma.sync.aligned.m16n8k16.row.col.f32.bf16.bf16.f32 "
        "{%0,%1,%2,%3}, {%4,%5,%6,%7}, {%8,%9}, {%0,%1,%2,%3};"
        : "+f"(d[0]), "+f"(d[1]), "+f"(d[2]), "+f"(d[3])
        : "r"(a[0]), "r"(a[1]), "r"(a[2]), "r"(a[3]), "r"(b0), "r"(b1));
}

/* ------------------------------------------------------------------ */
/* pass 1: abs-sum partials over W                                     */
/* ------------------------------------------------------------------ */
__global__ void k_reduce(const float* __restrict__ w) {
    __shared__ float sm[256];
    const float4* w4 = reinterpret_cast<const float4*>(w);
    int idx = blockIdx.x * 256 + threadIdx.x;
    int stride = gridDim.x * 256;
    float s0 = 0.f, s1 = 0.f, s2 = 0.f, s3 = 0.f;
    int i = idx;
    for (; i + 3 * stride < N4; i += 4 * stride) {
        float4 a = w4[i];
        float4 b = w4[i + stride];
        float4 c = w4[i + 2 * stride];
        float4 d = w4[i + 3 * stride];
        s0 += fabsf(a.x) + fabsf(a.y) + fabsf(a.z) + fabsf(a.w);
        s1 += fabsf(b.x) + fabsf(b.y) + fabsf(b.z) + fabsf(b.w);
        s2 += fabsf(c.x) + fabsf(c.y) + fabsf(c.z) + fabsf(c.w);
        s3 += fabsf(d.x) + fabsf(d.y) + fabsf(d.z) + fabsf(d.w);
    }
    for (; i < N4; i += stride) {
        float4 a = w4[i];
        s0 += fabsf(a.x) + fabsf(a.y) + fabsf(a.z) + fabsf(a.w);
    }
    sm[threadIdx.x] = (s0 + s1) + (s2 + s3);
    __syncthreads();
    for (int o = 128; o > 0; o >>= 1) {
        if (threadIdx.x < o) sm[threadIdx.x] += sm[threadIdx.x + o];
        __syncthreads();
    }
    if (threadIdx.x == 0) g_partials[blockIdx.x] = sm[0];
}

/* ------------------------------------------------------------------ */
/* pass 2: finish reduction in double, publish scale + threshold bits  */
/* ------------------------------------------------------------------ */
__global__ void k_finalize() {
    __shared__ double sd[256];
    double s = 0.0;
    for (int i = threadIdx.x; i < RBLOCKS; i += 256) s += (double)g_partials[i];
    sd[threadIdx.x] = s;
    __syncthreads();
    for (int o = 128; o > 0; o >>= 1) {
        if (threadIdx.x < o) sd[threadIdx.x] += sd[threadIdx.x + o];
        __syncthreads();
    }
    if (threadIdx.x == 0) {
        double mean = sd[0] / (double)NELEM;
        float am = fmaxf((float)mean, 1e-5f);
        g_scale = am;
        g_thr_bits = __float_as_uint(0.7f * am);
    }
}

/* ------------------------------------------------------------------ */
/* pass 3: split x into bf16 hi/lo                                     */
/* ------------------------------------------------------------------ */
__global__ void k_xsplit(const float* __restrict__ x) {
    int i = blockIdx.x * blockDim.x + threadIdx.x;
    if (i < TOK * IN_F) {
        float v = x[i];
        __nv_bfloat16 h = __float2bfloat16(v);
        g_xhi[i] = h;
        g_xlo[i] = __float2bfloat16(v - __bfloat162float(h));
    }
}

/* ------------------------------------------------------------------ */
/* pass 4: partial dequant-GEMM. grid = 86*8 = 688 CTAs x 512 thr.     */
/* Item = (M-tile of 128 outputs, K-chunk of 512). 16 warps, each      */
/* warp: 8 outputs (1 n8) x 32 tokens (2 m16). Writes g_part[ks].      */
/* ------------------------------------------------------------------ */
__global__ __launch_bounds__(512, 1) void k_gemm(const float* __restrict__ w) {
    extern __shared__ __align__(16) char smem[];
    uint32_t sbase = smem_u32(smem);
    const uint32_t lo_off = TOK * PK * 2;          /* bytes to lo buffer */

    const int tid = threadIdx.x;
    const int lane = tid & 31;
    const int wid = tid >> 5;

    const int tile = blockIdx.x >> 3;
    const int ks = blockIdx.x & 7;
    const int k0 = ks * KSP;

    /* ---- stage x chunk (hi & lo) into padded SMEM ---- */
    {
        const uint4* srch = reinterpret_cast<const uint4*>(g_xhi);
        const uint4* srcl = reinterpret_cast<const uint4*>(g_xlo);
#pragma unroll
        for (int e = 0; e < (TOK * KSP / 8) / 512; e++) {
            int g = e * 512 + tid;                 /* 8-elem group id */
            int tok = g >> 6;                      /* KSP/8 = 64 groups/row */
            int kg = g & 63;
            uint4 hv = srch[(tok * IN_F + k0) / 8 + kg];
            uint4 lv = srcl[(tok * IN_F + k0) / 8 + kg];
            uint32_t dst = sbase + (uint32_t)(tok * PK + kg * 8) * 2;
            asm volatile("st.shared.v4.b32 [%0], {%1,%2,%3,%4};"
                         :: "r"(dst), "r"(hv.x), "r"(hv.y), "r"(hv.z), "r"(hv.w)
                         : "memory");
            asm volatile("st.shared.v4.b32 [%0], {%1,%2,%3,%4};"
                         :: "r"(dst + lo_off), "r"(lv.x), "r"(lv.y), "r"(lv.z), "r"(lv.w)
                         : "memory");
        }
    }

    const uint32_t thr = g_thr_bits;
    const int o_base = tile * 128 + wid * 8;
    const int kq = 2 * (lane & 3);
    const int nrow = lane >> 2;

    const float* wr = w + (size_t)(o_base + nrow) * IN_F + k0 + kq;

    /* ldmatrix per-thread source row/col inside a 16x16 A tile */
    const int mrow = ((lane >> 3) & 1) * 8 + (lane & 7);
    const int mcol = (lane >> 4) * 8;
    const uint32_t am0 = sbase + (uint32_t)((0 * 16 + mrow) * PK + mcol) * 2;
    const uint32_t am1 = sbase + (uint32_t)((1 * 16 + mrow) * PK + mcol) * 2;

    float acc[2][4];
#pragma unroll
    for (int t = 0; t < 2; t++)
#pragma unroll
        for (int r = 0; r < 4; r++) acc[t][r] = 0.f;

    __syncthreads();

#pragma unroll 4
    for (int kk = 0; kk < KSP; kk += 16) {
        /* W loads first: two independent LDG.64 per thread */
        float2 u0 = *reinterpret_cast<const float2*>(wr + kk);
        float2 u1 = *reinterpret_cast<const float2*>(wr + kk + 8);

        uint32_t ah0[4], ah1[4], al0[4], al1[4];
        ldsm_x4(ah0, am0 + kk * 2);
        ldsm_x4(ah1, am1 + kk * 2);
        ldsm_x4(al0, am0 + kk * 2 + lo_off);
        ldsm_x4(al1, am1 + kk * 2 + lo_off);

        uint32_t b0 = tpack(u0.x, u0.y, thr);
        uint32_t b1 = tpack(u1.x, u1.y, thr);

        mma_bf16(acc[0], ah0, b0, b1);
        mma_bf16(acc[1], ah1, b0, b1);
        mma_bf16(acc[0], al0, b0, b1);
        mma_bf16(acc[1], al1, b0, b1);
    }

    /* ---- epilogue: write partials (unscaled) ---- */
    float* dst = g_part[ks];
#pragma unroll
    for (int tt = 0; tt < 2; tt++) {
        int tok = tt * 16 + (lane >> 2);
        int o = o_base + kq;
        float2 lo2, hi2;
        lo2.x = acc[tt][0];
        lo2.y = acc[tt][1];
        hi2.x = acc[tt][2];
        hi2.y = acc[tt][3];
        *reinterpret_cast<float2*>(dst + (size_t)tok * OUT_F + o) = lo2;
        *reinterpret_cast<float2*>(dst + (size_t)(tok + 8) * OUT_F + o) = hi2;
    }
}

/* ------------------------------------------------------------------ */
/* pass 5: combine 8 partials, apply scale                             */
/* ------------------------------------------------------------------ */
__global__ void k_combine(float* __restrict__ out) {
    const float scale = g_scale;
    int i = blockIdx.x * 256 + threadIdx.x;      /* float4 index */
    if (i < TOK * OUT_F / 4) {
        float4 s = reinterpret_cast<const float4*>(g_part[0])[i];
#pragma unroll
        for (int p = 1; p < SPLITS; p++) {
            float4 v = reinterpret_cast<const float4*>(g_part[p])[i];
            s.x += v.x; s.y += v.y; s.z += v.z; s.w += v.w;
        }
        s.x *= scale; s.y *= scale; s.z *= scale; s.w *= scale;
        reinterpret_cast<float4*>(out)[i] = s;
    }
}

/* ------------------------------------------------------------------ */
extern "C" void kernel_launch(void* const* d_in, const int* in_sizes, int n_in,
                              void* d_out, int out_size) {
    const float* x = (const float*)d_in[0];
    const float* w = (const float*)d_in[1];
    float* out = (float*)d_out;
    (void)in_sizes; (void)n_in; (void)out_size;

    cudaFuncSetAttribute(k_gemm, cudaFuncAttributeMaxDynamicSharedMemorySize,
                         GEMM_SMEM);

    k_reduce<<<RBLOCKS, 256>>>(w);
    k_finalize<<<1, 256>>>();
    k_xsplit<<<(TOK * IN_F + 255) / 256, 256>>>(x);
    k_gemm<<<MTILES * SPLITS, 512, GEMM_SMEM>>>(w);
    k_combine<<<(TOK * OUT_F / 4 + 255) / 256, 256>>>(out);
}

// round 9
// speedup vs baseline: 1.3502x; 1.0647x over previous
#include <cuda_runtime.h>
#include <cuda_bf16.h>
#include <cstdint>
#include <cstddef>

#define IN_F 4096
#define OUT_F 11008
#define TOK 32
#define NELEM (OUT_F * IN_F)     /* 45,088,768 */
#define N4 (NELEM / 4)           /* 11,272,192 */
#define RBLOCKS 1184

#define MTILES 86                /* OUT_F / 128 */
#define SPLITS 8
#define KSP (IN_F / SPLITS)      /* 512 k per item */
#define PK (KSP + 8)             /* padded row: conflict-free ldmatrix */
#define GEMM_SMEM (2 * TOK * PK * 2)   /* hi+lo bf16: 66,560 B */

/* ------------------------------------------------------------------ */
/* device globals (scratch — no allocations allowed)                   */
/* ------------------------------------------------------------------ */
__device__ float                        g_partials[RBLOCKS];
__device__ float                        g_scale;
__device__ unsigned                     g_thr_bits;
__device__ __align__(16) __nv_bfloat16  g_xhi[TOK * IN_F];
__device__ __align__(16) __nv_bfloat16  g_xlo[TOK * IN_F];
__device__ float                        g_part[SPLITS][TOK * OUT_F];

/* ------------------------------------------------------------------ */
__device__ __forceinline__ uint32_t smem_u32(const void* p) {
    uint32_t a;
    asm("{ .reg .u64 t; cvta.to.shared.u64 t, %1; cvt.u32.u64 %0, t; }"
        : "=r"(a) : "l"(p));
    return a;
}

/* ternarize one fp32 (bit pattern) -> bf16 half in {0xBF80, 0x0000, 0x3F80} */
__device__ __forceinline__ uint32_t tern(uint32_t u, uint32_t thr) {
    uint32_t h = 0x3F80u | ((u >> 16) & 0x8000u);
    return ((u & 0x7FFFFFFFu) > thr) ? h : 0u;
}

__device__ __forceinline__ uint32_t tpack(float a, float b, uint32_t thr) {
    return __byte_perm(tern(__float_as_uint(a), thr),
                       tern(__float_as_uint(b), thr), 0x5410);
}

__device__ __forceinline__ void ldsm_x4(uint32_t* r, uint32_t addr) {
    asm volatile("ldmatrix.sync.aligned.m8n8.x4.shared.b16 {%0,%1,%2,%3}, [%4];"
                 : "=r"(r[0]), "=r"(r[1]), "=r"(r[2]), "=r"(r[3]) : "r"(addr));
}

__device__ __forceinline__ void mma_bf16(float* d, const uint32_t* a,
                                         uint32_t b0, uint32_t b1) {
    asm volatile(
        "mma.sync.aligned.m16n8k16.row.col.f32.bf16.bf16.f32 "
        "{%0,%1,%2,%3}, {%4,%5,%6,%7}, {%8,%9}, {%0,%1,%2,%3};"
        : "+f"(d[0]), "+f"(d[1]), "+f"(d[2]), "+f"(d[3])
        : "r"(a[0]), "r"(a[1]), "r"(a[2]), "r"(a[3]), "r"(b0), "r"(b1));
}

/* ------------------------------------------------------------------ */
/* pass 1: abs-sum partials over W                                     */
/* ------------------------------------------------------------------ */
__global__ void k_reduce(const float* __restrict__ w) {
    __shared__ float sm[256];
    const float4* w4 = reinterpret_cast<const float4*>(w);
    int idx = blockIdx.x * 256 + threadIdx.x;
    int stride = gridDim.x * 256;
    float s0 = 0.f, s1 = 0.f, s2 = 0.f, s3 = 0.f;
    int i = idx;
    for (; i + 3 * stride < N4; i += 4 * stride) {
        float4 a = w4[i];
        float4 b = w4[i + stride];
        float4 c = w4[i + 2 * stride];
        float4 d = w4[i + 3 * stride];
        s0 += fabsf(a.x) + fabsf(a.y) + fabsf(a.z) + fabsf(a.w);
        s1 += fabsf(b.x) + fabsf(b.y) + fabsf(b.z) + fabsf(b.w);
        s2 += fabsf(c.x) + fabsf(c.y) + fabsf(c.z) + fabsf(c.w);
        s3 += fabsf(d.x) + fabsf(d.y) + fabsf(d.z) + fabsf(d.w);
    }
    for (; i < N4; i += stride) {
        float4 a = w4[i];
        s0 += fabsf(a.x) + fabsf(a.y) + fabsf(a.z) + fabsf(a.w);
    }
    sm[threadIdx.x] = (s0 + s1) + (s2 + s3);
    __syncthreads();
    for (int o = 128; o > 0; o >>= 1) {
        if (threadIdx.x < o) sm[threadIdx.x] += sm[threadIdx.x + o];
        __syncthreads();
    }
    if (threadIdx.x == 0) g_partials[blockIdx.x] = sm[0];
}

/* ------------------------------------------------------------------ */
/* pass 2: finish reduction in double, publish scale + threshold bits  */
/* ------------------------------------------------------------------ */
__global__ void k_finalize() {
    __shared__ double sd[256];
    double s = 0.0;
    for (int i = threadIdx.x; i < RBLOCKS; i += 256) s += (double)g_partials[i];
    sd[threadIdx.x] = s;
    __syncthreads();
    for (int o = 128; o > 0; o >>= 1) {
        if (threadIdx.x < o) sd[threadIdx.x] += sd[threadIdx.x + o];
        __syncthreads();
    }
    if (threadIdx.x == 0) {
        double mean = sd[0] / (double)NELEM;
        float am = fmaxf((float)mean, 1e-5f);
        g_scale = am;
        g_thr_bits = __float_as_uint(0.7f * am);
    }
}

/* ------------------------------------------------------------------ */
/* pass 3: split x into bf16 hi/lo                                     */
/* ------------------------------------------------------------------ */
__global__ void k_xsplit(const float* __restrict__ x) {
    int i = blockIdx.x * blockDim.x + threadIdx.x;
    if (i < TOK * IN_F) {
        float v = x[i];
        __nv_bfloat16 h = __float2bfloat16(v);
        g_xhi[i] = h;
        g_xlo[i] = __float2bfloat16(v - __bfloat162float(h));
    }
}

/* ------------------------------------------------------------------ */
/* pass 4: partial dequant-GEMM. grid = 86*8 = 688 CTAs x 256 thr,     */
/* 2 CTAs/SM. Item = (M-tile of 128 outputs, K-chunk of 512).          */
/* 8 warps, each: 16 outputs (2 n8 tiles) x 32 tokens (2 m16 tiles).   */
/* Tiles processed in DESCENDING address order to hit the L2 leftovers */
/* from k_reduce's sweep. Writes g_part[ks] (unscaled).                */
/* ------------------------------------------------------------------ */
__global__ __launch_bounds__(256, 2) void k_gemm(const float* __restrict__ w) {
    extern __shared__ __align__(16) char smem[];
    uint32_t sbase = smem_u32(smem);
    const uint32_t lo_off = TOK * PK * 2;          /* bytes to lo buffer */

    const int tid = threadIdx.x;
    const int lane = tid & 31;
    const int wid = tid >> 5;

    const int tile = (MTILES - 1) - (blockIdx.x >> 3);   /* reverse order */
    const int ks = blockIdx.x & 7;
    const int k0 = ks * KSP;

    /* ---- stage x chunk (hi & lo) into padded SMEM ---- */
    {
        const uint4* srch = reinterpret_cast<const uint4*>(g_xhi);
        const uint4* srcl = reinterpret_cast<const uint4*>(g_xlo);
#pragma unroll
        for (int e = 0; e < (TOK * KSP / 8) / 256; e++) {
            int g = e * 256 + tid;                 /* 8-elem group id */
            int tok = g >> 6;                      /* KSP/8 = 64 groups/row */
            int kg = g & 63;
            uint4 hv = srch[(tok * IN_F + k0) / 8 + kg];
            uint4 lv = srcl[(tok * IN_F + k0) / 8 + kg];
            uint32_t dst = sbase + (uint32_t)(tok * PK + kg * 8) * 2;
            asm volatile("st.shared.v4.b32 [%0], {%1,%2,%3,%4};"
                         :: "r"(dst), "r"(hv.x), "r"(hv.y), "r"(hv.z), "r"(hv.w)
                         : "memory");
            asm volatile("st.shared.v4.b32 [%0], {%1,%2,%3,%4};"
                         :: "r"(dst + lo_off), "r"(lv.x), "r"(lv.y), "r"(lv.z), "r"(lv.w)
                         : "memory");
        }
    }

    const uint32_t thr = g_thr_bits;
    const int o_base = tile * 128 + wid * 16;
    const int kq = 2 * (lane & 3);
    const int nrow = lane >> 2;

    const float* w0 = w + (size_t)(o_base + nrow) * IN_F + k0 + kq;
    const float* w1 = w0 + (size_t)8 * IN_F;

    /* ldmatrix per-thread source row/col inside a 16x16 A tile */
    const int mrow = ((lane >> 3) & 1) * 8 + (lane & 7);
    const int mcol = (lane >> 4) * 8;
    const uint32_t am0 = sbase + (uint32_t)((0 * 16 + mrow) * PK + mcol) * 2;
    const uint32_t am1 = sbase + (uint32_t)((1 * 16 + mrow) * PK + mcol) * 2;

    float acc[2][2][4];
#pragma unroll
    for (int t = 0; t < 2; t++)
#pragma unroll
        for (int n = 0; n < 2; n++)
#pragma unroll
            for (int r = 0; r < 4; r++) acc[t][n][r] = 0.f;

    __syncthreads();

#pragma unroll 2
    for (int kk = 0; kk < KSP; kk += 16) {
        /* W loads first: four independent LDG.64 per thread */
        float2 u00 = *reinterpret_cast<const float2*>(w0 + kk);
        float2 u01 = *reinterpret_cast<const float2*>(w0 + kk + 8);
        float2 u10 = *reinterpret_cast<const float2*>(w1 + kk);
        float2 u11 = *reinterpret_cast<const float2*>(w1 + kk + 8);

        /* A fragments for both token tiles, hi and lo */
        uint32_t ah0[4], ah1[4], al0[4], al1[4];
        ldsm_x4(ah0, am0 + kk * 2);
        ldsm_x4(ah1, am1 + kk * 2);
        ldsm_x4(al0, am0 + kk * 2 + lo_off);
        ldsm_x4(al1, am1 + kk * 2 + lo_off);

        /* ternarize -> B fragments */
        uint32_t b00 = tpack(u00.x, u00.y, thr);
        uint32_t b01 = tpack(u01.x, u01.y, thr);
        uint32_t b10 = tpack(u10.x, u10.y, thr);
        uint32_t b11 = tpack(u11.x, u11.y, thr);

        mma_bf16(acc[0][0], ah0, b00, b01);
        mma_bf16(acc[1][0], ah1, b00, b01);
        mma_bf16(acc[0][1], ah0, b10, b11);
        mma_bf16(acc[1][1], ah1, b10, b11);
        mma_bf16(acc[0][0], al0, b00, b01);
        mma_bf16(acc[1][0], al1, b00, b01);
        mma_bf16(acc[0][1], al0, b10, b11);
        mma_bf16(acc[1][1], al1, b10, b11);
    }

    /* ---- epilogue: write partials (unscaled) ---- */
    float* dst = g_part[ks];
#pragma unroll
    for (int tt = 0; tt < 2; tt++) {
#pragma unroll
        for (int nt = 0; nt < 2; nt++) {
            int tok = tt * 16 + (lane >> 2);
            int o = o_base + nt * 8 + kq;
            float2 lo2, hi2;
            lo2.x = acc[tt][nt][0];
            lo2.y = acc[tt][nt][1];
            hi2.x = acc[tt][nt][2];
            hi2.y = acc[tt][nt][3];
            *reinterpret_cast<float2*>(dst + (size_t)tok * OUT_F + o) = lo2;
            *reinterpret_cast<float2*>(dst + (size_t)(tok + 8) * OUT_F + o) = hi2;
        }
    }
}

/* ------------------------------------------------------------------ */
/* pass 5: combine 8 partials, apply scale                             */
/* ------------------------------------------------------------------ */
__global__ void k_combine(float* __restrict__ out) {
    const float scale = g_scale;
    int i = blockIdx.x * 256 + threadIdx.x;      /* float4 index */
    if (i < TOK * OUT_F / 4) {
        float4 s = reinterpret_cast<const float4*>(g_part[0])[i];
#pragma unroll
        for (int p = 1; p < SPLITS; p++) {
            float4 v = reinterpret_cast<const float4*>(g_part[p])[i];
            s.x += v.x; s.y += v.y; s.z += v.z; s.w += v.w;
        }
        s.x *= scale; s.y *= scale; s.z *= scale; s.w *= scale;
        reinterpret_cast<float4*>(out)[i] = s;
    }
}

/* ------------------------------------------------------------------ */
extern "C" void kernel_launch(void* const* d_in, const int* in_sizes, int n_in,
                              void* d_out, int out_size) {
    const float* x = (const float*)d_in[0];
    const float* w = (const float*)d_in[1];
    float* out = (float*)d_out;
    (void)in_sizes; (void)n_in; (void)out_size;

    cudaFuncSetAttribute(k_gemm, cudaFuncAttributeMaxDynamicSharedMemorySize,
                         GEMM_SMEM);

    k_reduce<<<RBLOCKS, 256>>>(w);
    k_finalize<<<1, 256>>>();
    k_xsplit<<<(TOK * IN_F + 255) / 256, 256>>>(x);
    k_gemm<<<MTILES * SPLITS, 256, GEMM_SMEM>>>(w);
    k_combine<<<(TOK * OUT_F / 4 + 255) / 256, 256>>>(out);
}

// round 10
// speedup vs baseline: 1.3822x; 1.0237x over previous
#include <cuda_runtime.h>
#include <cuda_bf16.h>
#include <cstdint>
#include <cstddef>

#define IN_F 4096
#define OUT_F 11008
#define TOK 32
#define NELEM (OUT_F * IN_F)     /* 45,088,768 */
#define N4 (NELEM / 4)           /* 11,272,192 */
#define RBLOCKS 1184

#define MTILES 86                /* OUT_F / 128 */
#define SPLITS 8
#define KSP (IN_F / SPLITS)      /* 512 k per item */
#define PK (KSP + 8)             /* padded row: conflict-free ldmatrix */
#define GEMM_SMEM (2 * TOK * PK * 2)   /* hi+lo bf16: 66,560 B */

/* ------------------------------------------------------------------ */
/* device globals (scratch — no allocations allowed)                   */
/* ------------------------------------------------------------------ */
__device__ float                        g_partials[RBLOCKS];
__device__ float                        g_scale;
__device__ unsigned                     g_thr_bits;
__device__ __align__(16) __nv_bfloat16  g_xhi[TOK * IN_F];
__device__ __align__(16) __nv_bfloat16  g_xlo[TOK * IN_F];
__device__ float                        g_part[SPLITS][TOK * OUT_F];

/* ------------------------------------------------------------------ */
__device__ __forceinline__ uint32_t smem_u32(const void* p) {
    uint32_t a;
    asm("{ .reg .u64 t; cvta.to.shared.u64 t, %1; cvt.u32.u64 %0, t; }"
        : "=r"(a) : "l"(p));
    return a;
}

/* ternarize one fp32 (bit pattern) -> bf16 half in {0xBF80, 0x0000, 0x3F80} */
__device__ __forceinline__ uint32_t tern(uint32_t u, uint32_t thr) {
    uint32_t h = 0x3F80u | ((u >> 16) & 0x8000u);
    return ((u & 0x7FFFFFFFu) > thr) ? h : 0u;
}

__device__ __forceinline__ uint32_t tpack(float a, float b, uint32_t thr) {
    return __byte_perm(tern(__float_as_uint(a), thr),
                       tern(__float_as_uint(b), thr), 0x5410);
}

__device__ __forceinline__ void ldsm_x4(uint32_t* r, uint32_t addr) {
    asm volatile("ldmatrix.sync.aligned.m8n8.x4.shared.b16 {%0,%1,%2,%3}, [%4];"
                 : "=r"(r[0]), "=r"(r[1]), "=r"(r[2]), "=r"(r[3]) : "r"(addr));
}

__device__ __forceinline__ void mma_bf16(float* d, const uint32_t* a,
                                         uint32_t b0, uint32_t b1) {
    asm volatile(
        "mma.sync.aligned.m16n8k16.row.col.f32.bf16.bf16.f32 "
        "{%0,%1,%2,%3}, {%4,%5,%6,%7}, {%8,%9}, {%0,%1,%2,%3};"
        : "+f"(d[0]), "+f"(d[1]), "+f"(d[2]), "+f"(d[3])
        : "r"(a[0]), "r"(a[1]), "r"(a[2]), "r"(a[3]), "r"(b0), "r"(b1));
}

/* ------------------------------------------------------------------ */
/* pass 1: abs-sum partials over W                                     */
/* ------------------------------------------------------------------ */
__global__ void k_reduce(const float* __restrict__ w) {
    __shared__ float sm[256];
    const float4* w4 = reinterpret_cast<const float4*>(w);
    int idx = blockIdx.x * 256 + threadIdx.x;
    int stride = gridDim.x * 256;
    float s0 = 0.f, s1 = 0.f, s2 = 0.f, s3 = 0.f;
    int i = idx;
    for (; i + 3 * stride < N4; i += 4 * stride) {
        float4 a = w4[i];
        float4 b = w4[i + stride];
        float4 c = w4[i + 2 * stride];
        float4 d = w4[i + 3 * stride];
        s0 += fabsf(a.x) + fabsf(a.y) + fabsf(a.z) + fabsf(a.w);
        s1 += fabsf(b.x) + fabsf(b.y) + fabsf(b.z) + fabsf(b.w);
        s2 += fabsf(c.x) + fabsf(c.y) + fabsf(c.z) + fabsf(c.w);
        s3 += fabsf(d.x) + fabsf(d.y) + fabsf(d.z) + fabsf(d.w);
    }
    for (; i < N4; i += stride) {
        float4 a = w4[i];
        s0 += fabsf(a.x) + fabsf(a.y) + fabsf(a.z) + fabsf(a.w);
    }
    sm[threadIdx.x] = (s0 + s1) + (s2 + s3);
    __syncthreads();
    for (int o = 128; o > 0; o >>= 1) {
        if (threadIdx.x < o) sm[threadIdx.x] += sm[threadIdx.x + o];
        __syncthreads();
    }
    if (threadIdx.x == 0) g_partials[blockIdx.x] = sm[0];
}

/* ------------------------------------------------------------------ */
/* pass 2: finish reduction in double, publish scale + threshold bits  */
/* ------------------------------------------------------------------ */
__global__ void k_finalize() {
    __shared__ double sd[256];
    double s = 0.0;
    for (int i = threadIdx.x; i < RBLOCKS; i += 256) s += (double)g_partials[i];
    sd[threadIdx.x] = s;
    __syncthreads();
    for (int o = 128; o > 0; o >>= 1) {
        if (threadIdx.x < o) sd[threadIdx.x] += sd[threadIdx.x + o];
        __syncthreads();
    }
    if (threadIdx.x == 0) {
        double mean = sd[0] / (double)NELEM;
        float am = fmaxf((float)mean, 1e-5f);
        g_scale = am;
        g_thr_bits = __float_as_uint(0.7f * am);
    }
}

/* ------------------------------------------------------------------ */
/* pass 3: split x into bf16 hi/lo                                     */
/* ------------------------------------------------------------------ */
__global__ void k_xsplit(const float* __restrict__ x) {
    int i = blockIdx.x * blockDim.x + threadIdx.x;
    if (i < TOK * IN_F) {
        float v = x[i];
        __nv_bfloat16 h = __float2bfloat16(v);
        g_xhi[i] = h;
        g_xlo[i] = __float2bfloat16(v - __bfloat162float(h));
    }
}

/* ------------------------------------------------------------------ */
/* pass 4: partial dequant-GEMM. grid = 86*8 = 688 CTAs x 256 thr,     */
/* 3 CTAs/SM. Item = (M-tile of 128 outputs, K-chunk of 512).          */
/* 8 warps, each: 16 outputs (2 n8 tiles) x 32 tokens (2 m16 tiles).   */
/* Distance-1 software prefetch of W; tiles in descending order for    */
/* L2 leftovers from k_reduce. Writes g_part[ks] (unscaled).           */
/* ------------------------------------------------------------------ */
__global__ __launch_bounds__(256, 3) void k_gemm(const float* __restrict__ w) {
    extern __shared__ __align__(16) char smem[];
    uint32_t sbase = smem_u32(smem);
    const uint32_t lo_off = TOK * PK * 2;          /* bytes to lo buffer */

    const int tid = threadIdx.x;
    const int lane = tid & 31;
    const int wid = tid >> 5;

    const int tile = (MTILES - 1) - (blockIdx.x >> 3);   /* reverse order */
    const int ks = blockIdx.x & 7;
    const int k0 = ks * KSP;

    /* ---- stage x chunk (hi & lo) into padded SMEM ---- */
    {
        const uint4* srch = reinterpret_cast<const uint4*>(g_xhi);
        const uint4* srcl = reinterpret_cast<const uint4*>(g_xlo);
#pragma unroll
        for (int e = 0; e < (TOK * KSP / 8) / 256; e++) {
            int g = e * 256 + tid;                 /* 8-elem group id */
            int tok = g >> 6;                      /* KSP/8 = 64 groups/row */
            int kg = g & 63;
            uint4 hv = srch[(tok * IN_F + k0) / 8 + kg];
            uint4 lv = srcl[(tok * IN_F + k0) / 8 + kg];
            uint32_t dst = sbase + (uint32_t)(tok * PK + kg * 8) * 2;
            asm volatile("st.shared.v4.b32 [%0], {%1,%2,%3,%4};"
                         :: "r"(dst), "r"(hv.x), "r"(hv.y), "r"(hv.z), "r"(hv.w)
                         : "memory");
            asm volatile("st.shared.v4.b32 [%0], {%1,%2,%3,%4};"
                         :: "r"(dst + lo_off), "r"(lv.x), "r"(lv.y), "r"(lv.z), "r"(lv.w)
                         : "memory");
        }
    }

    const uint32_t thr = g_thr_bits;
    const int o_base = tile * 128 + wid * 16;
    const int kq = 2 * (lane & 3);
    const int nrow = lane >> 2;

    const float* w0 = w + (size_t)(o_base + nrow) * IN_F + k0 + kq;
    const float* w1 = w0 + (size_t)8 * IN_F;

    /* ldmatrix per-thread source row/col inside a 16x16 A tile */
    const int mrow = ((lane >> 3) & 1) * 8 + (lane & 7);
    const int mcol = (lane >> 4) * 8;
    const uint32_t am0 = sbase + (uint32_t)((0 * 16 + mrow) * PK + mcol) * 2;
    const uint32_t am1 = sbase + (uint32_t)((1 * 16 + mrow) * PK + mcol) * 2;

    float acc[2][2][4];
#pragma unroll
    for (int t = 0; t < 2; t++)
#pragma unroll
        for (int n = 0; n < 2; n++)
#pragma unroll
            for (int r = 0; r < 4; r++) acc[t][n][r] = 0.f;

    __syncthreads();

    /* ---- software-pipelined main loop: prefetch W for kk+16 ---- */
    float2 c00 = *reinterpret_cast<const float2*>(w0);
    float2 c01 = *reinterpret_cast<const float2*>(w0 + 8);
    float2 c10 = *reinterpret_cast<const float2*>(w1);
    float2 c11 = *reinterpret_cast<const float2*>(w1 + 8);

#pragma unroll 2
    for (int kk = 0; kk < KSP; kk += 16) {
        float2 n00, n01, n10, n11;
        if (kk + 16 < KSP) {
            n00 = *reinterpret_cast<const float2*>(w0 + kk + 16);
            n01 = *reinterpret_cast<const float2*>(w0 + kk + 24);
            n10 = *reinterpret_cast<const float2*>(w1 + kk + 16);
            n11 = *reinterpret_cast<const float2*>(w1 + kk + 24);
        }

        uint32_t ah0[4], ah1[4], al0[4], al1[4];
        ldsm_x4(ah0, am0 + kk * 2);
        ldsm_x4(ah1, am1 + kk * 2);
        ldsm_x4(al0, am0 + kk * 2 + lo_off);
        ldsm_x4(al1, am1 + kk * 2 + lo_off);

        uint32_t b00 = tpack(c00.x, c00.y, thr);
        uint32_t b01 = tpack(c01.x, c01.y, thr);
        uint32_t b10 = tpack(c10.x, c10.y, thr);
        uint32_t b11 = tpack(c11.x, c11.y, thr);

        mma_bf16(acc[0][0], ah0, b00, b01);
        mma_bf16(acc[1][0], ah1, b00, b01);
        mma_bf16(acc[0][1], ah0, b10, b11);
        mma_bf16(acc[1][1], ah1, b10, b11);
        mma_bf16(acc[0][0], al0, b00, b01);
        mma_bf16(acc[1][0], al1, b00, b01);
        mma_bf16(acc[0][1], al0, b10, b11);
        mma_bf16(acc[1][1], al1, b10, b11);

        c00 = n00; c01 = n01; c10 = n10; c11 = n11;
    }

    /* ---- epilogue: write partials (unscaled) ---- */
    float* dst = g_part[ks];
#pragma unroll
    for (int tt = 0; tt < 2; tt++) {
#pragma unroll
        for (int nt = 0; nt < 2; nt++) {
            int tok = tt * 16 + (lane >> 2);
            int o = o_base + nt * 8 + kq;
            float2 lo2, hi2;
            lo2.x = acc[tt][nt][0];
            lo2.y = acc[tt][nt][1];
            hi2.x = acc[tt][nt][2];
            hi2.y = acc[tt][nt][3];
            *reinterpret_cast<float2*>(dst + (size_t)tok * OUT_F + o) = lo2;
            *reinterpret_cast<float2*>(dst + (size_t)(tok + 8) * OUT_F + o) = hi2;
        }
    }
}

/* ------------------------------------------------------------------ */
/* pass 5: combine 8 partials, apply scale                             */
/* ------------------------------------------------------------------ */
__global__ void k_combine(float* __restrict__ out) {
    const float scale = g_scale;
    int i = blockIdx.x * 256 + threadIdx.x;      /* float4 index */
    if (i < TOK * OUT_F / 4) {
        float4 s = reinterpret_cast<const float4*>(g_part[0])[i];
#pragma unroll
        for (int p = 1; p < SPLITS; p++) {
            float4 v = reinterpret_cast<const float4*>(g_part[p])[i];
            s.x += v.x; s.y += v.y; s.z += v.z; s.w += v.w;
        }
        s.x *= scale; s.y *= scale; s.z *= scale; s.w *= scale;
        reinterpret_cast<float4*>(out)[i] = s;
    }
}

/* ------------------------------------------------------------------ */
extern "C" void kernel_launch(void* const* d_in, const int* in_sizes, int n_in,
                              void* d_out, int out_size) {
    const float* x = (const float*)d_in[0];
    const float* w = (const float*)d_in[1];
    float* out = (float*)d_out;
    (void)in_sizes; (void)n_in; (void)out_size;

    cudaFuncSetAttribute(k_gemm, cudaFuncAttributeMaxDynamicSharedMemorySize,
                         GEMM_SMEM);

    k_reduce<<<RBLOCKS, 256>>>(w);
    k_finalize<<<1, 256>>>();
    k_xsplit<<<(TOK * IN_F + 255) / 256, 256>>>(x);
    k_gemm<<<MTILES * SPLITS, 256, GEMM_SMEM>>>(w);
    k_combine<<<(TOK * OUT_F / 4 + 255) / 256, 256>>>(out);
}

// round 12
// speedup vs baseline: 1.4825x; 1.0726x over previous
#include <cuda_runtime.h>
#include <cuda_bf16.h>
#include <cstdint>
#include <cstddef>

#define IN_F 4096
#define OUT_F 11008
#define TOK 32
#define NELEM (OUT_F * IN_F)     /* 45,088,768 */
#define N4 (NELEM / 4)           /* 11,272,192 */
#define RBLOCKS 1184

#define MTILES 86                /* OUT_F / 128 */
#define SPLITS 16
#define KSP (IN_F / SPLITS)      /* 256 k per item */
#define PK (KSP + 8)             /* 264: padded row for ldmatrix */
#define XSMEM (2 * TOK * PK * 2) /* hi+lo bf16: 33,792 B */

/* per-warp W ring: 4 buffers x 16 rows x 144B */
#define WROW 144
#define WBUF (16 * WROW)         /* 2304 B */
#define WRING (4 * WBUF)         /* 9216 B per warp */
#define GEMM_SMEM (XSMEM + 8 * WRING)   /* 107,520 B -> 2 CTAs/SM */

/* ------------------------------------------------------------------ */
__device__ float                        g_partials[RBLOCKS];
__device__ float                        g_scale;
__device__ unsigned                     g_thr_bits;
__device__ __align__(16) __nv_bfloat16  g_xhi[TOK * IN_F];
__device__ __align__(16) __nv_bfloat16  g_xlo[TOK * IN_F];
__device__ float                        g_part[SPLITS][TOK * OUT_F];

/* ------------------------------------------------------------------ */
__device__ __forceinline__ uint32_t smem_u32(const void* p) {
    uint32_t a;
    asm("{ .reg .u64 t; cvta.to.shared.u64 t, %1; cvt.u32.u64 %0, t; }"
        : "=r"(a) : "l"(p));
    return a;
}

/* ternarize one fp32 (bit pattern) -> bf16 half in {0xBF80, 0x0000, 0x3F80} */
__device__ __forceinline__ uint32_t tern(uint32_t u, uint32_t thr) {
    uint32_t h = 0x3F80u | ((u >> 16) & 0x8000u);
    return ((u & 0x7FFFFFFFu) > thr) ? h : 0u;
}

__device__ __forceinline__ uint32_t tpack(float a, float b, uint32_t thr) {
    return __byte_perm(tern(__float_as_uint(a), thr),
                       tern(__float_as_uint(b), thr), 0x5410);
}

__device__ __forceinline__ void ldsm_x4(uint32_t* r, uint32_t addr) {
    asm volatile("ldmatrix.sync.aligned.m8n8.x4.shared.b16 {%0,%1,%2,%3}, [%4];"
                 : "=r"(r[0]), "=r"(r[1]), "=r"(r[2]), "=r"(r[3]) : "r"(addr));
}

__device__ __forceinline__ void mma_bf16(float* d, const uint32_t* a,
                                         uint32_t b0, uint32_t b1) {
    asm volatile(
        "mma.sync.aligned.m16n8k16.row.col.f32.bf16.bf16.f32 "
        "{%0,%1,%2,%3}, {%4,%5,%6,%7}, {%8,%9}, {%0,%1,%2,%3};"
        : "+f"(d[0]), "+f"(d[1]), "+f"(d[2]), "+f"(d[3])
        : "r"(a[0]), "r"(a[1]), "r"(a[2]), "r"(a[3]), "r"(b0), "r"(b1));
}

__device__ __forceinline__ void cp16(uint32_t dst, const void* src) {
    asm volatile("cp.async.cg.shared.global [%0], [%1], 16;"
                 :: "r"(dst), "l"(src) : "memory");
}

__device__ __forceinline__ float2 lds_v2(uint32_t addr) {
    float2 v;
    asm volatile("ld.shared.v2.f32 {%0,%1}, [%2];"
                 : "=f"(v.x), "=f"(v.y) : "r"(addr));
    return v;
}

/* ------------------------------------------------------------------ */
/* pass 1: abs-sum partials over W                                     */
/* ------------------------------------------------------------------ */
__global__ void k_reduce(const float* __restrict__ w) {
    __shared__ float sm[256];
    const float4* w4 = reinterpret_cast<const float4*>(w);
    int idx = blockIdx.x * 256 + threadIdx.x;
    int stride = gridDim.x * 256;
    float s0 = 0.f, s1 = 0.f, s2 = 0.f, s3 = 0.f;
    int i = idx;
    for (; i + 3 * stride < N4; i += 4 * stride) {
        float4 a = w4[i];
        float4 b = w4[i + stride];
        float4 c = w4[i + 2 * stride];
        float4 d = w4[i + 3 * stride];
        s0 += fabsf(a.x) + fabsf(a.y) + fabsf(a.z) + fabsf(a.w);
        s1 += fabsf(b.x) + fabsf(b.y) + fabsf(b.z) + fabsf(b.w);
        s2 += fabsf(c.x) + fabsf(c.y) + fabsf(c.z) + fabsf(c.w);
        s3 += fabsf(d.x) + fabsf(d.y) + fabsf(d.z) + fabsf(d.w);
    }
    for (; i < N4; i += stride) {
        float4 a = w4[i];
        s0 += fabsf(a.x) + fabsf(a.y) + fabsf(a.z) + fabsf(a.w);
    }
    sm[threadIdx.x] = (s0 + s1) + (s2 + s3);
    __syncthreads();
    for (int o = 128; o > 0; o >>= 1) {
        if (threadIdx.x < o) sm[threadIdx.x] += sm[threadIdx.x + o];
        __syncthreads();
    }
    if (threadIdx.x == 0) g_partials[blockIdx.x] = sm[0];
}

/* ------------------------------------------------------------------ */
__global__ void k_finalize() {
    __shared__ double sd[256];
    double s = 0.0;
    for (int i = threadIdx.x; i < RBLOCKS; i += 256) s += (double)g_partials[i];
    sd[threadIdx.x] = s;
    __syncthreads();
    for (int o = 128; o > 0; o >>= 1) {
        if (threadIdx.x < o) sd[threadIdx.x] += sd[threadIdx.x + o];
        __syncthreads();
    }
    if (threadIdx.x == 0) {
        double mean = sd[0] / (double)NELEM;
        float am = fmaxf((float)mean, 1e-5f);
        g_scale = am;
        g_thr_bits = __float_as_uint(0.7f * am);
    }
}

/* ------------------------------------------------------------------ */
__global__ void k_xsplit(const float* __restrict__ x) {
    int i = blockIdx.x * blockDim.x + threadIdx.x;
    if (i < TOK * IN_F) {
        float v = x[i];
        __nv_bfloat16 h = __float2bfloat16(v);
        g_xhi[i] = h;
        g_xlo[i] = __float2bfloat16(v - __bfloat162float(h));
    }
}

/* ------------------------------------------------------------------ */
/* pass 4: partial dequant-GEMM. grid = 86*16 = 1376 CTAs x 256 thr,   */
/* 2 CTAs/SM. Item = (M-tile 128 outs, K-chunk 256). 8 warps x 16 outs.*/
/* W flows GMEM->SMEM via per-warp cp.async ring (4 bufs x k32); no    */
/* CTA barrier in the mainloop. One commit_group per stage (empty in   */
/* the tail) keeps wait_group 3 exact for every consumed buffer.       */
/* ------------------------------------------------------------------ */
__global__ __launch_bounds__(256, 2) void k_gemm(const float* __restrict__ w) {
    extern __shared__ __align__(16) char smem[];
    uint32_t sbase = smem_u32(smem);
    const uint32_t lo_off = TOK * PK * 2;

    const int tid = threadIdx.x;
    const int lane = tid & 31;
    const int wid = tid >> 5;

    const int tile = (MTILES - 1) - (blockIdx.x >> 4);   /* reverse order */
    const int ks = blockIdx.x & 15;
    const int k0 = ks * KSP;

    const int o_base = tile * 128 + wid * 16;

    /* ---- per-warp W ring setup ---- */
    const uint32_t wring = sbase + XSMEM + wid * WRING;
    const int lrow = lane >> 3;                 /* 0..3: row within op  */
    const int lcol = lane & 7;                  /* 16B column           */
    const float* gw = w + (size_t)o_base * IN_F + k0;
    const float* gsrc = gw + (size_t)lrow * IN_F + lcol * 4;
    const uint32_t sdst = wring + lrow * WROW + lcol * 16;

    /* issue stage s into buffer b (k columns s*32..s*32+31) */
#define W_ISSUE(s, b)                                                        \
    do {                                                                     \
        _Pragma("unroll")                                                    \
        for (int op = 0; op < 4; op++)                                       \
            cp16(sdst + (b) * WBUF + op * 4 * WROW,                          \
                 gsrc + (size_t)op * 4 * IN_F + (s) * 32);                   \
        asm volatile("cp.async.commit_group;" ::: "memory");                 \
    } while (0)

    /* prologue: fill all 4 buffers (overlaps with x staging below) */
    W_ISSUE(0, 0); W_ISSUE(1, 1); W_ISSUE(2, 2); W_ISSUE(3, 3);

    /* ---- stage x chunk (hi & lo) into padded SMEM ---- */
    {
        const uint4* srch = reinterpret_cast<const uint4*>(g_xhi);
        const uint4* srcl = reinterpret_cast<const uint4*>(g_xlo);
#pragma unroll
        for (int e = 0; e < (TOK * KSP / 8) / 256; e++) {
            int g = e * 256 + tid;
            int tok = g >> 5;                   /* KSP/8 = 32 groups/row */
            int kg = g & 31;
            uint4 hv = srch[(tok * IN_F + k0) / 8 + kg];
            uint4 lv = srcl[(tok * IN_F + k0) / 8 + kg];
            uint32_t dst = sbase + (uint32_t)(tok * PK + kg * 8) * 2;
            asm volatile("st.shared.v4.b32 [%0], {%1,%2,%3,%4};"
                         :: "r"(dst), "r"(hv.x), "r"(hv.y), "r"(hv.z), "r"(hv.w)
                         : "memory");
            asm volatile("st.shared.v4.b32 [%0], {%1,%2,%3,%4};"
                         :: "r"(dst + lo_off), "r"(lv.x), "r"(lv.y), "r"(lv.z), "r"(lv.w)
                         : "memory");
        }
    }

    const uint32_t thr = g_thr_bits;
    const int kq = 2 * (lane & 3);
    const int nrow = lane >> 2;

    /* W consumption addresses inside a buffer */
    const uint32_t wrd = wring + nrow * WROW;            /* row nrow      */

    /* ldmatrix A addresses */
    const int mrow = ((lane >> 3) & 1) * 8 + (lane & 7);
    const int mcol = (lane >> 4) * 8;
    const uint32_t am0 = sbase + (uint32_t)((0 * 16 + mrow) * PK + mcol) * 2;
    const uint32_t am1 = sbase + (uint32_t)((1 * 16 + mrow) * PK + mcol) * 2;

    float acc[2][2][4];
#pragma unroll
    for (int t = 0; t < 2; t++)
#pragma unroll
        for (int n = 0; n < 2; n++)
#pragma unroll
            for (int r = 0; r < 4; r++) acc[t][n][r] = 0.f;

    __syncthreads();   /* x tiles visible to all warps */

    /* ---- mainloop: 8 stages of k32, per-warp async pipeline ---- */
#pragma unroll 1
    for (int s = 0; s < 8; s++) {
        asm volatile("cp.async.wait_group 3;" ::: "memory");
        __syncwarp();

        const uint32_t wb = wrd + (s & 3) * WBUF;
#pragma unroll
        for (int j = 0; j < 2; j++) {
            const int kk = s * 32 + j * 16;
            const uint32_t o4 = (uint32_t)(j * 16 + kq) * 4;

            float2 u00 = lds_v2(wb + o4);
            float2 u01 = lds_v2(wb + o4 + 32);
            float2 u10 = lds_v2(wb + 8 * WROW + o4);
            float2 u11 = lds_v2(wb + 8 * WROW + o4 + 32);

            uint32_t ah0[4], ah1[4], al0[4], al1[4];
            ldsm_x4(ah0, am0 + kk * 2);
            ldsm_x4(ah1, am1 + kk * 2);
            ldsm_x4(al0, am0 + kk * 2 + lo_off);
            ldsm_x4(al1, am1 + kk * 2 + lo_off);

            uint32_t b00 = tpack(u00.x, u00.y, thr);
            uint32_t b01 = tpack(u01.x, u01.y, thr);
            uint32_t b10 = tpack(u10.x, u10.y, thr);
            uint32_t b11 = tpack(u11.x, u11.y, thr);

            mma_bf16(acc[0][0], ah0, b00, b01);
            mma_bf16(acc[1][0], ah1, b00, b01);
            mma_bf16(acc[0][1], ah0, b10, b11);
            mma_bf16(acc[1][1], ah1, b10, b11);
            mma_bf16(acc[0][0], al0, b00, b01);
            mma_bf16(acc[1][0], al1, b00, b01);
            mma_bf16(acc[0][1], al0, b10, b11);
            mma_bf16(acc[1][1], al1, b10, b11);
        }

        __syncwarp();
        if (s + 4 < 8) {
            W_ISSUE(s + 4, s & 3);
        } else {
            /* tail: empty group keeps the wait_group 3 arithmetic exact */
            asm volatile("cp.async.commit_group;" ::: "memory");
        }
    }

    /* ---- epilogue: write partials (unscaled) ---- */
    float* dst = g_part[ks];
#pragma unroll
    for (int tt = 0; tt < 2; tt++) {
#pragma unroll
        for (int nt = 0; nt < 2; nt++) {
            int tok = tt * 16 + (lane >> 2);
            int o = o_base + nt * 8 + kq;
            float2 lo2, hi2;
            lo2.x = acc[tt][nt][0];
            lo2.y = acc[tt][nt][1];
            hi2.x = acc[tt][nt][2];
            hi2.y = acc[tt][nt][3];
            *reinterpret_cast<float2*>(dst + (size_t)tok * OUT_F + o) = lo2;
            *reinterpret_cast<float2*>(dst + (size_t)(tok + 8) * OUT_F + o) = hi2;
        }
    }
#undef W_ISSUE
}

/* ------------------------------------------------------------------ */
/* pass 5: combine 16 partials, apply scale                            */
/* ------------------------------------------------------------------ */
__global__ void k_combine(float* __restrict__ out) {
    const float scale = g_scale;
    int i = blockIdx.x * 256 + threadIdx.x;      /* float4 index */
    if (i < TOK * OUT_F / 4) {
        float4 s = reinterpret_cast<const float4*>(g_part[0])[i];
#pragma unroll
        for (int p = 1; p < SPLITS; p++) {
            float4 v = reinterpret_cast<const float4*>(g_part[p])[i];
            s.x += v.x; s.y += v.y; s.z += v.z; s.w += v.w;
        }
        s.x *= scale; s.y *= scale; s.z *= scale; s.w *= scale;
        reinterpret_cast<float4*>(out)[i] = s;
    }
}

/* ------------------------------------------------------------------ */
extern "C" void kernel_launch(void* const* d_in, const int* in_sizes, int n_in,
                              void* d_out, int out_size) {
    const float* x = (const float*)d_in[0];
    const float* w = (const float*)d_in[1];
    float* out = (float*)d_out;
    (void)in_sizes; (void)n_in; (void)out_size;

    cudaFuncSetAttribute(k_gemm, cudaFuncAttributeMaxDynamicSharedMemorySize,
                         GEMM_SMEM);

    k_reduce<<<RBLOCKS, 256>>>(w);
    k_finalize<<<1, 256>>>();
    k_xsplit<<<(TOK * IN_F + 255) / 256, 256>>>(x);
    k_gemm<<<MTILES * SPLITS, 256, GEMM_SMEM>>>(w);
    k_combine<<<(TOK * OUT_F / 4 + 255) / 256, 256>>>(out);
}